// round 14
// baseline (speedup 1.0000x reference)
#include <cuda_runtime.h>
#include <cuda_fp16.h>
#include <math.h>
#include <stdint.h>

// ---------------------------------------------------------------------------
// Bert_Traj_Model: B=32, S=512, D=768, H=12, dh=64, FF=3072, L=12, fp32 I/O.
// Round 14: cache-policy tuning. A-operand (shared by the 2 co-resident CTAs)
// and attention Q/K/V loads use cp.async.ca (L1+L2); weights stay .cg.
// Everything else identical to round 13.
// ---------------------------------------------------------------------------

namespace {
constexpr int kB  = 32;
constexpr int kS  = 512;
constexpr int kD  = 768;
constexpr int kH  = 12;
constexpr int kFF = 3072;
constexpr int kL  = 12;
constexpr int kM  = kB * kS;               // 16384 rows
constexpr int kQKV = 3 * kD;               // 2304
constexpr int kStageBytes = 16384;         // A 8K, B 8K
constexpr int kNS = 6;
constexpr int kSmemBytes = kNS * kStageBytes;       // 96KB
constexpr int kAttnSmem = 16384 + 2 * 16384 + 512;  // 49664
}

// ----------------------------- scratch (no allocs allowed) ------------------
__device__ float g_h  [(size_t)kM * kD];
__device__ float g_tmp[(size_t)kM * kD];
__device__ float g_pe [kS * kD];
__device__ float g_bqkv[kL * kQKV];
__device__ __half g_hn [(size_t)kM * kD];
__device__ __half g_qkv[(size_t)kM * kQKV];
__device__ __half g_o  [(size_t)kM * kD];
__device__ __half g_ff [(size_t)kM * kFF];
// pre-tiled fp16 weights: blocks of 128(n) x 32(k), row-major in block
__device__ __half g_wqkv[(size_t)kL * kD * kQKV];
__device__ __half g_wo  [(size_t)kL * kD * kD];
__device__ __half g_w1  [(size_t)kL * kD * kFF];
__device__ __half g_w2  [(size_t)kL * kFF * kD];

// ----------------------------- PTX helpers ---------------------------------
__device__ __forceinline__ uint32_t smem_u32(const void* p) {
    uint32_t a;
    asm("{ .reg .u64 t; cvta.to.shared.u64 t, %1; cvt.u32.u64 %0, t; }" : "=r"(a) : "l"(p));
    return a;
}
#define CP16(dst, src)  asm volatile("cp.async.cg.shared.global [%0], [%1], 16;" :: "r"(dst), "l"(src))
#define CP16A(dst, src) asm volatile("cp.async.ca.shared.global [%0], [%1], 16;" :: "r"(dst), "l"(src))
#define CP_COMMIT()     asm volatile("cp.async.commit_group;" ::: "memory")
#define CP_WAIT(n)      asm volatile("cp.async.wait_group %0;" :: "n"(n) : "memory")

#define LDSM4(r0, r1, r2, r3, a)                                                \
    asm volatile("ldmatrix.sync.aligned.m8n8.x4.shared.b16 {%0,%1,%2,%3}, [%4];" \
                 : "=r"(r0), "=r"(r1), "=r"(r2), "=r"(r3) : "r"(a))
#define LDSM4T(r0, r1, r2, r3, a)                                               \
    asm volatile("ldmatrix.sync.aligned.m8n8.x4.trans.shared.b16 {%0,%1,%2,%3}, [%4];" \
                 : "=r"(r0), "=r"(r1), "=r"(r2), "=r"(r3) : "r"(a))
#define MMA_F16(d, a, b)                                                        \
    asm volatile("mma.sync.aligned.m16n8k16.row.col.f32.f16.f16.f32 "           \
                 "{%0,%1,%2,%3}, {%4,%5,%6,%7}, {%8,%9}, {%0,%1,%2,%3};"        \
                 : "+f"((d)[0]), "+f"((d)[1]), "+f"((d)[2]), "+f"((d)[3])       \
                 : "r"((a)[0]), "r"((a)[1]), "r"((a)[2]), "r"((a)[3]),          \
                   "r"((b)[0]), "r"((b)[1]))

__device__ __forceinline__ uint32_t pack2h(float a, float b) {
    __half2 t = __halves2half2(__float2half_rn(a), __float2half_rn(b));
    return *(uint32_t*)&t;
}
__device__ __forceinline__ uint32_t soff(int row, int ch) {   // 64B rows
    return (uint32_t)(row * 64 + ((ch ^ ((row >> 1) & 3)) << 4));
}
__device__ __forceinline__ uint32_t swz(int row, int ch) {    // 128B rows
    return (uint32_t)(row * 128 + ((ch ^ (row & 7)) << 4));
}

// ---------------------------------------------------------------------------
// Weight prep (tile-mapped, division-free, coalesced).
// ---------------------------------------------------------------------------
__global__ void __launch_bounds__(256)
prep_w_tile(const float* __restrict__ W, __half* __restrict__ dst,
            int K, int Nsrc, int Ntot, int ntoff, float scale) {
    const int kc = blockIdx.x, nt = blockIdx.y, l = blockIdx.z;
    const int lane = threadIdx.x & 31, w = threadIdx.x >> 5;
    const int nl8 = lane >> 2, kkg = lane & 3;
    const int kcnt = K >> 5;
    const float* src = W + (size_t)l * K * Nsrc + (size_t)(kc * 32) * Nsrc + nt * 128;
    __half* dtile = dst + (size_t)l * K * Ntot
                  + ((size_t)((ntoff + nt) * kcnt + kc)) * 4096;
    #pragma unroll
    for (int task = 0; task < 2; task++) {
        const int nlb = (w + task * 8) * 8;        // 0,8,...,120
        const float* s0 = src + nlb + nl8;
        uint4 o;
        __half* oh = (__half*)&o;
        #pragma unroll
        for (int j = 0; j < 8; j++)
            oh[j] = __float2half_rn(s0[(size_t)(kkg * 8 + j) * Nsrc] * scale);
        *(uint4*)(dtile + (nlb + nl8) * 32 + kkg * 8) = o;
    }
}

__global__ void bias_qkv_kernel(const float* __restrict__ bq, const float* __restrict__ bk,
                                const float* __restrict__ bv, float* __restrict__ dst) {
    int idx = blockIdx.x * blockDim.x + threadIdx.x;
    if (idx >= kL * kQKV) return;
    int l = idx / kQKV, j = idx - l * kQKV;
    float v;
    if (j < kD)            v = 0.125f * bq[l * kD + j];
    else if (j < 2 * kD)   v = bk[l * kD + j - kD];
    else                   v = bv[l * kD + j - 2 * kD];
    dst[idx] = v;
}

// ---------------------------------------------------------------------------
// mma_gemm: C[M,N] = epi(A @ W + bias). A single fp16 (.ca), W fp16 tiles (.cg).
// modes: 1=+Res fp32 out, 2=relu fp16 out, 3=fp16 out.
// 128x128 CTA tile, 8 warps of 32x64, 6-stage cp.async, 1 barrier / 2 chunks.
// ---------------------------------------------------------------------------
__global__ void __launch_bounds__(256, 2)
mma_gemm(const __half* __restrict__ Ah, const __half* __restrict__ Bw,
         const float* __restrict__ bias, const float* __restrict__ Res,
         float* __restrict__ C, __half* __restrict__ Ch,
         int N, int K, int mode) {
    extern __shared__ char smem[];
    const uint32_t sb = smem_u32(smem);
    const int tid = threadIdx.x;
    const int lane = tid & 31, wid = tid >> 5;
    const int wm = (wid & 3) * 32, wn = (wid >> 2) * 64;
    const int m0 = blockIdx.y * 128, n0 = blockIdx.x * 128;
    const int iters = K >> 5;                       // even (>= 24)
    const size_t btile = (size_t)blockIdx.x * iters * 4096;

    float acc[2][8][4];
    #pragma unroll
    for (int a = 0; a < 2; a++)
        #pragma unroll
        for (int b = 0; b < 8; b++)
            #pragma unroll
            for (int c = 0; c < 4; c++) acc[a][b][c] = 0.0f;

    auto load_stage = [&](int c, int s) {
        const uint32_t st = sb + (uint32_t)s * kStageBytes;
        #pragma unroll
        for (int p = 0; p < 2; p++) {
            int idx = p * 256 + tid;
            int row = idx >> 2, ch = idx & 3;
            uint32_t so = soff(row, ch);
            const __half* gA = Ah + (size_t)(m0 + row) * K + c * 32 + ch * 8;
            size_t boff = btile + (size_t)c * 4096 + row * 32 + ch * 8;
            CP16A(st + so, gA);                    // A: L1+L2 (shared with co-CTA)
            CP16(st + 8192 + so, Bw + boff);       // B: L2 only
        }
        CP_COMMIT();
    };

    auto compute_stage = [&](int s) {
        const uint32_t base = sb + (uint32_t)s * kStageBytes;
        #pragma unroll
        for (int ks = 0; ks < 2; ks++) {
            const int kc = ks * 2;
            uint32_t ah[2][4], bh[8][2];
            #pragma unroll
            for (int mf = 0; mf < 2; mf++) {
                int row = wm + mf * 16 + (lane & 15);
                int ch = kc + (lane >> 4);
                LDSM4(ah[mf][0], ah[mf][1], ah[mf][2], ah[mf][3], base + soff(row, ch));
            }
            #pragma unroll
            for (int nb = 0; nb < 4; nb++) {
                int row = wn + nb * 16 + (lane & 7) + ((lane >> 4) << 3);
                int ch = kc + ((lane >> 3) & 1);
                LDSM4(bh[2 * nb][0], bh[2 * nb][1], bh[2 * nb + 1][0], bh[2 * nb + 1][1],
                      base + 8192 + soff(row, ch));
            }
            #pragma unroll
            for (int mf = 0; mf < 2; mf++)
                #pragma unroll
                for (int nf = 0; nf < 8; nf++)
                    MMA_F16(acc[mf][nf], ah[mf], bh[nf]);
        }
    };

    load_stage(0, 0);
    load_stage(1, 1);
    load_stage(2, 2);
    load_stage(3, 3);

    int s = 0;                                   // stage of chunk c
    for (int c = 0; c < iters; c += 2) {
        if (iters - c - 2 >= 2) CP_WAIT(2);
        else CP_WAIT(0);
        __syncthreads();
        if (c + 4 < iters) {
            int s4 = s + 4 >= 6 ? s - 2 : s + 4;
            int s5 = s4 + 1 >= 6 ? 0 : s4 + 1;
            load_stage(c + 4, s4);
            load_stage(c + 5, s5);
        }
        compute_stage(s);
        int s1 = s + 1 >= 6 ? 0 : s + 1;
        compute_stage(s1);
        s = s + 2 >= 6 ? s - 4 : s + 2;
    }

    #pragma unroll
    for (int mf = 0; mf < 2; mf++) {
        #pragma unroll
        for (int h = 0; h < 2; h++) {
            const int r = m0 + wm + mf * 16 + (lane >> 2) + h * 8;
            #pragma unroll
            for (int nf = 0; nf < 8; nf++) {
                const int cc = n0 + wn + nf * 8 + (lane & 3) * 2;
                float v0 = acc[mf][nf][h * 2 + 0] + bias[cc];
                float v1 = acc[mf][nf][h * 2 + 1] + bias[cc + 1];
                size_t base = (size_t)r * N + cc;
                if (mode == 3) {
                    *(uint32_t*)(Ch + base) = pack2h(v0, v1);
                } else if (mode == 2) {
                    v0 = fmaxf(v0, 0.0f);
                    v1 = fmaxf(v1, 0.0f);
                    *(uint32_t*)(Ch + base) = pack2h(v0, v1);
                } else {
                    float2 rr = *(const float2*)(Res + base);
                    float2 o;
                    o.x = v0 + rr.x;
                    o.y = v1 + rr.y;
                    *(float2*)(C + base) = o;
                }
            }
        }
    }
}

// ---------------------------------------------------------------------------
// attn_mma: flash attention, all-single-fp16 operands (fp32 accumulators).
// Causal tile-skip: kt < min(8, 2*qt+2). Q/K/V loads .ca (cross-block reuse).
// smem: Qh 16K | 2 stages x (Kh 8K|Vh 8K) | pad 512   (2 CTA/SM)
// ---------------------------------------------------------------------------
__global__ void __launch_bounds__(256, 2)
attn_mma(const __half* __restrict__ qh_g, const __half* __restrict__ kh_g,
         const __half* __restrict__ vh_g, int rstride,
         const int* __restrict__ xtok, const int* __restrict__ ltp,
         __half* __restrict__ oh_g) {
    extern __shared__ char smem[];
    const uint32_t sb = smem_u32(smem);
    const int tid = threadIdx.x, lane = tid & 31, w = tid >> 5;
    const int qt = blockIdx.x, hh = blockIdx.y, b = blockIdx.z;
    const int lt = ltp[0];
    const int nkt = (2 * qt + 2) < 8 ? (2 * qt + 2) : 8;   // live key tiles

    const uint32_t QH = sb;
    const uint32_t STG = sb + 16384;      // + s*16384: Kh 8K, Vh 8K
    char* padp = smem + 16384 + 2 * 16384;

    #pragma unroll
    for (int i = 0; i < 2; i++)
        padp[tid + i * 256] = (xtok[b * kS + tid + i * 256] > 0) ? 1 : 0;

    const size_t qgbase = ((size_t)(b * kS + qt * 128)) * rstride + hh * 64;
    #pragma unroll
    for (int i = 0; i < 4; i++) {
        int idx = i * 256 + tid;
        int row = idx >> 3, ch = idx & 7;
        CP16A(QH + swz(row, ch), qh_g + qgbase + (size_t)row * rstride + ch * 8);
    }
    CP_COMMIT();

    auto load_kv = [&](int kt, int s) {
        const uint32_t st = STG + (uint32_t)s * 16384;
        const size_t gb = ((size_t)(b * kS + kt * 64)) * rstride + hh * 64;
        #pragma unroll
        for (int i = 0; i < 2; i++) {
            int idx = i * 256 + tid;
            int row = idx >> 3, ch = idx & 7;
            uint32_t so = swz(row, ch);
            size_t go = gb + (size_t)row * rstride + ch * 8;
            CP16A(st + so,        kh_g + go);
            CP16A(st + 8192 + so, vh_g + go);
        }
        CP_COMMIT();
    };

    load_kv(0, 0);
    load_kv(1, 1);

    uint32_t qfh[4][4];
    float oacc[8][4];
    #pragma unroll
    for (int i = 0; i < 8; i++)
        #pragma unroll
        for (int j = 0; j < 4; j++) oacc[i][j] = 0.0f;
    float m_[2] = {-INFINITY, -INFINITY}, l_[2] = {0.0f, 0.0f};

    const int rbase = qt * 128 + w * 16 + (lane >> 2);

    for (int kt = 0; kt < nkt; kt++) {
        if (kt < nkt - 1) { CP_WAIT(1); } else { CP_WAIT(0); }
        __syncthreads();

        if (kt == 0) {
            #pragma unroll
            for (int ks = 0; ks < 4; ks++) {
                int row = w * 16 + (lane & 15);
                int ch = ks * 2 + (lane >> 4);
                LDSM4(qfh[ks][0], qfh[ks][1], qfh[ks][2], qfh[ks][3], QH + swz(row, ch));
            }
        }

        const uint32_t st = STG + (uint32_t)(kt & 1) * 16384;
        const uint32_t KHs = st, VHs = st + 8192;

        float s4[8][4];
        #pragma unroll
        for (int i = 0; i < 8; i++)
            #pragma unroll
            for (int j = 0; j < 4; j++) s4[i][j] = 0.0f;

        #pragma unroll
        for (int ks = 0; ks < 4; ks++) {
            uint32_t bh[8][2];
            #pragma unroll
            for (int kg = 0; kg < 4; kg++) {
                int row = kg * 16 + (lane & 7) + ((lane >> 4) << 3);
                int ch = ks * 2 + ((lane >> 3) & 1);
                LDSM4(bh[2 * kg][0], bh[2 * kg][1], bh[2 * kg + 1][0], bh[2 * kg + 1][1],
                      KHs + swz(row, ch));
            }
            #pragma unroll
            for (int nf = 0; nf < 8; nf++)
                MMA_F16(s4[nf], qfh[ks], bh[nf]);
        }

        #pragma unroll
        for (int nf = 0; nf < 8; nf++) {
            int col = kt * 64 + nf * 8 + (lane & 3) * 2;
            bool p0 = padp[col] != 0;
            bool p1 = padp[col + 1] != 0;
            bool c0lt = col < lt, c1lt = (col + 1) < lt;
            s4[nf][0] = (p0 && (col <= rbase || c0lt))         ? s4[nf][0] : -1.0e9f;
            s4[nf][1] = (p1 && (col + 1 <= rbase || c1lt))     ? s4[nf][1] : -1.0e9f;
            s4[nf][2] = (p0 && (col <= rbase + 8 || c0lt))     ? s4[nf][2] : -1.0e9f;
            s4[nf][3] = (p1 && (col + 1 <= rbase + 8 || c1lt)) ? s4[nf][3] : -1.0e9f;
        }

        #pragma unroll
        for (int r = 0; r < 2; r++) {
            float tm = -INFINITY;
            #pragma unroll
            for (int nf = 0; nf < 8; nf++)
                tm = fmaxf(tm, fmaxf(s4[nf][2 * r], s4[nf][2 * r + 1]));
            tm = fmaxf(tm, __shfl_xor_sync(0xffffffffu, tm, 1));
            tm = fmaxf(tm, __shfl_xor_sync(0xffffffffu, tm, 2));
            float nm = fmaxf(m_[r], tm);
            float al = __expf(m_[r] - nm);
            m_[r] = nm;
            float ts = 0.0f;
            #pragma unroll
            for (int nf = 0; nf < 8; nf++) {
                float p0 = __expf(s4[nf][2 * r] - nm);
                float p1 = __expf(s4[nf][2 * r + 1] - nm);
                s4[nf][2 * r] = p0;
                s4[nf][2 * r + 1] = p1;
                ts += p0 + p1;
            }
            ts += __shfl_xor_sync(0xffffffffu, ts, 1);
            ts += __shfl_xor_sync(0xffffffffu, ts, 2);
            l_[r] = l_[r] * al + ts;
            #pragma unroll
            for (int nf = 0; nf < 8; nf++) {
                oacc[nf][2 * r] *= al;
                oacc[nf][2 * r + 1] *= al;
            }
        }

        // ---- O += P V (single fp16 products) ----
        #pragma unroll
        for (int kv = 0; kv < 4; kv++) {
            uint32_t pah[4];
            pah[0] = pack2h(s4[2 * kv][0], s4[2 * kv][1]);
            pah[1] = pack2h(s4[2 * kv][2], s4[2 * kv][3]);
            pah[2] = pack2h(s4[2 * kv + 1][0], s4[2 * kv + 1][1]);
            pah[3] = pack2h(s4[2 * kv + 1][2], s4[2 * kv + 1][3]);
            #pragma unroll
            for (int dg = 0; dg < 4; dg++) {
                int row = kv * 16 + (lane & 7) + ((lane >> 3) & 1) * 8;
                int ch = dg * 2 + (lane >> 4);
                uint32_t so = swz(row, ch);
                uint32_t vh0, vh1, vh2, vh3;
                LDSM4T(vh0, vh1, vh2, vh3, VHs + so);
                uint32_t bfh0[2] = {vh0, vh1}, bfh1[2] = {vh2, vh3};
                MMA_F16(oacc[dg * 2], pah, bfh0);
                MMA_F16(oacc[dg * 2 + 1], pah, bfh1);
            }
        }

        __syncthreads();
        if (kt + 2 < nkt) load_kv(kt + 2, kt & 1);
    }

    float inv0 = 1.0f / l_[0], inv1 = 1.0f / l_[1];
    const int row0 = qt * 128 + w * 16 + (lane >> 2);
    #pragma unroll
    for (int nf = 0; nf < 8; nf++) {
        int col = hh * 64 + nf * 8 + (lane & 3) * 2;
        size_t b0 = ((size_t)(b * kS + row0)) * kD + col;
        size_t b1 = ((size_t)(b * kS + row0 + 8)) * kD + col;
        *(uint32_t*)(oh_g + b0) = pack2h(oacc[nf][0] * inv0, oacc[nf][1] * inv0);
        *(uint32_t*)(oh_g + b1) = pack2h(oacc[nf][2] * inv1, oacc[nf][3] * inv1);
    }
}

// ---------------------------------------------------------------------------
// Positional encoding table (fp64, 393K elems) + memory-bound embed.
// ---------------------------------------------------------------------------
__global__ void pe_kernel(float* __restrict__ pe) {
    int idx = blockIdx.x * blockDim.x + threadIdx.x;
    if (idx >= kS * kD) return;
    int s = idx / kD;
    int j = idx - s * kD;
    int i2 = j & ~1;
    double ang = (double)s * pow(10000.0, -(double)i2 / (double)kD);
    pe[idx] = (j & 1) ? (float)cos(ang) : (float)sin(ang);
}

__global__ void embed_kernel(const int* __restrict__ x, const int* __restrict__ tim,
                             const float* __restrict__ tok_emb,
                             const float* __restrict__ time_emb,
                             const float* __restrict__ pe, float* __restrict__ out) {
    int idx = blockIdx.x * blockDim.x + threadIdx.x;
    if (idx >= kM * kD) return;
    int bs = idx / kD;
    int j = idx - bs * kD;
    int s = bs & (kS - 1);
    out[idx] = tok_emb[(size_t)x[bs] * kD + j] + time_emb[(size_t)tim[bs] * kD + j]
             + pe[s * kD + j];
}

// ----------------------------- LayerNorm ------------------------------------
__device__ __forceinline__ float block_reduce_sum(float v, float* sred) {
    #pragma unroll
    for (int o = 16; o > 0; o >>= 1) v += __shfl_xor_sync(0xffffffffu, v, o);
    int w = threadIdx.x >> 5;
    __syncthreads();
    if ((threadIdx.x & 31) == 0) sred[w] = v;
    __syncthreads();
    if (threadIdx.x == 0) {
        float t = sred[0];
        #pragma unroll
        for (int i = 1; i < 8; i++) t += sred[i];
        sred[0] = t;
    }
    __syncthreads();
    return sred[0];
}

__global__ void ln_kernel(const float* __restrict__ in, float* __restrict__ out,
                          const float* __restrict__ g, const float* __restrict__ b) {
    __shared__ float sred[8];
    int row = blockIdx.x, tid = threadIdx.x;
    const float* ip = in + (size_t)row * kD;
    float v0 = ip[tid], v1 = ip[tid + 256], v2 = ip[tid + 512];
    float sum = block_reduce_sum(v0 + v1 + v2, sred);
    float mu = sum * (1.0f / 768.0f);
    float d0 = v0 - mu, d1 = v1 - mu, d2 = v2 - mu;
    float sq = block_reduce_sum(d0 * d0 + d1 * d1 + d2 * d2, sred);
    float inv = 1.0f / sqrtf(sq * (1.0f / 768.0f) + 1e-6f);
    float* op = out + (size_t)row * kD;
    op[tid]       = g[tid]       * d0 * inv + b[tid];
    op[tid + 256] = g[tid + 256] * d1 * inv + b[tid + 256];
    op[tid + 512] = g[tid + 512] * d2 * inv + b[tid + 512];
}

// Per-layer LN (fp16 out): warp-per-row, no block barriers, float4 I/O.
__global__ void __launch_bounds__(256, 8)
ln_h16_kernel(const float* __restrict__ in, __half* __restrict__ out,
              const float* __restrict__ g, const float* __restrict__ b) {
    const int row = blockIdx.x * 8 + (threadIdx.x >> 5);
    const int lane = threadIdx.x & 31;
    const float* ip = in + (size_t)row * kD + lane * 4;

    float4 v[6];
    float sum = 0.0f;
    #pragma unroll
    for (int i = 0; i < 6; i++) {
        v[i] = *(const float4*)(ip + i * 128);
        sum += (v[i].x + v[i].y) + (v[i].z + v[i].w);
    }
    #pragma unroll
    for (int o = 16; o > 0; o >>= 1) sum += __shfl_xor_sync(0xffffffffu, sum, o);
    const float mu = sum * (1.0f / 768.0f);

    float sq = 0.0f;
    #pragma unroll
    for (int i = 0; i < 6; i++) {
        v[i].x -= mu; v[i].y -= mu; v[i].z -= mu; v[i].w -= mu;
        sq += (v[i].x * v[i].x + v[i].y * v[i].y) + (v[i].z * v[i].z + v[i].w * v[i].w);
    }
    #pragma unroll
    for (int o = 16; o > 0; o >>= 1) sq += __shfl_xor_sync(0xffffffffu, sq, o);
    const float inv = rsqrtf(sq * (1.0f / 768.0f) + 1e-6f);

    __half* op = out + (size_t)row * kD + lane * 4;
    #pragma unroll
    for (int i = 0; i < 6; i++) {
        float4 gv = *(const float4*)(g + lane * 4 + i * 128);
        float4 bv = *(const float4*)(b + lane * 4 + i * 128);
        float r0 = gv.x * v[i].x * inv + bv.x;
        float r1 = gv.y * v[i].y * inv + bv.y;
        float r2 = gv.z * v[i].z * inv + bv.z;
        float r3 = gv.w * v[i].w * inv + bv.w;
        uint2 pk = {pack2h(r0, r1), pack2h(r2, r3)};
        *(uint2*)(op + i * 128) = pk;
    }
}

// ---------------------------------------------------------------------------
extern "C" void kernel_launch(void* const* d_in, const int* in_sizes, int n_in,
                              void* d_out, int out_size) {
    const int*   x        = (const int*)d_in[0];
    const int*   tim      = (const int*)d_in[1];
    const int*   len_traj = (const int*)d_in[2];
    const float* tok_emb  = (const float*)d_in[3];
    const float* time_emb = (const float*)d_in[4];
    const float* emb_g    = (const float*)d_in[5];
    const float* emb_b    = (const float*)d_in[6];
    const float* Wq = (const float*)d_in[7];
    const float* bq = (const float*)d_in[8];
    const float* Wk = (const float*)d_in[9];
    const float* bk = (const float*)d_in[10];
    const float* Wv = (const float*)d_in[11];
    const float* bv = (const float*)d_in[12];
    const float* Wo = (const float*)d_in[13];
    const float* bo = (const float*)d_in[14];
    const float* ln1_g = (const float*)d_in[15];
    const float* ln1_b = (const float*)d_in[16];
    const float* W1 = (const float*)d_in[17];
    const float* b1 = (const float*)d_in[18];
    const float* W2 = (const float*)d_in[19];
    const float* b2 = (const float*)d_in[20];
    const float* ln2_g = (const float*)d_in[21];
    const float* ln2_b = (const float*)d_in[22];
    float* out = (float*)d_out;

    float *ph, *ptmp, *ppe, *pbqkv;
    __half *phn, *pqkv, *po, *pff;
    __half *pwqkv, *pwo, *pw1, *pw2;
    cudaGetSymbolAddress((void**)&ph,    g_h);
    cudaGetSymbolAddress((void**)&ptmp,  g_tmp);
    cudaGetSymbolAddress((void**)&ppe,   g_pe);
    cudaGetSymbolAddress((void**)&pbqkv, g_bqkv);
    cudaGetSymbolAddress((void**)&phn,   g_hn);
    cudaGetSymbolAddress((void**)&pqkv,  g_qkv);
    cudaGetSymbolAddress((void**)&po,    g_o);
    cudaGetSymbolAddress((void**)&pff,   g_ff);
    cudaGetSymbolAddress((void**)&pwqkv, g_wqkv);
    cudaGetSymbolAddress((void**)&pwo,   g_wo);
    cudaGetSymbolAddress((void**)&pw1,   g_w1);
    cudaGetSymbolAddress((void**)&pw2,   g_w2);

    cudaFuncSetAttribute(mma_gemm, cudaFuncAttributeMaxDynamicSharedMemorySize, kSmemBytes);
    cudaFuncSetAttribute(attn_mma, cudaFuncAttributeMaxDynamicSharedMemorySize, kAttnSmem);

    // weight prep: tile-mapped, division-free, coalesced
    prep_w_tile<<<dim3(24,  6, kL), 256>>>(Wq, pwqkv, kD,  kD,  kQKV, 0,  0.125f);
    prep_w_tile<<<dim3(24,  6, kL), 256>>>(Wk, pwqkv, kD,  kD,  kQKV, 6,  1.0f);
    prep_w_tile<<<dim3(24,  6, kL), 256>>>(Wv, pwqkv, kD,  kD,  kQKV, 12, 1.0f);
    prep_w_tile<<<dim3(24,  6, kL), 256>>>(Wo, pwo,   kD,  kD,  kD,   0,  1.0f);
    prep_w_tile<<<dim3(24, 24, kL), 256>>>(W1, pw1,   kD,  kFF, kFF,  0,  1.0f);
    prep_w_tile<<<dim3(96,  6, kL), 256>>>(W2, pw2,   kFF, kD,  kD,   0,  1.0f);
    bias_qkv_kernel<<<(kL * kQKV + 255) / 256, 256>>>(bq, bk, bv, pbqkv);

    pe_kernel<<<(kS * kD + 255) / 256, 256>>>(ppe);
    embed_kernel<<<(kM * kD + 255) / 256, 256>>>(x, tim, tok_emb, time_emb, ppe, ptmp);
    ln_kernel<<<kM, 256>>>(ptmp, ph, emb_g, emb_b);

    const dim3 gQKV(kQKV / 128, kM / 128);   // 18 x 128
    const dim3 gProj(kD / 128, kM / 128);    // 6 x 128
    const dim3 gFF1(kFF / 128, kM / 128);    // 24 x 128
    const dim3 gAttn(kS / 128, kH, kB);

    for (int i = 0; i < kL; i++) {
        const size_t wQ = (size_t)i * kD * kQKV;
        const size_t wD = (size_t)i * kD * kD;
        const size_t wF = (size_t)i * kD * kFF;
        ln_h16_kernel<<<kM / 8, 256>>>(ph, phn, ln1_g + i * kD, ln1_b + i * kD);
        mma_gemm<<<gQKV, 256, kSmemBytes>>>(phn, pwqkv + wQ, pbqkv + i * kQKV,
                                            nullptr, nullptr, pqkv, kQKV, kD, 3);
        attn_mma<<<gAttn, 256, kAttnSmem>>>(pqkv, pqkv + kD, pqkv + 2 * kD,
                                            kQKV, x, len_traj, po);
        mma_gemm<<<gProj, 256, kSmemBytes>>>(po, pwo + wD, bo + i * kD,
                                             ph, ph, nullptr, kD, kD, 1);
        ln_h16_kernel<<<kM / 8, 256>>>(ph, phn, ln2_g + i * kD, ln2_b + i * kD);
        mma_gemm<<<gFF1, 256, kSmemBytes>>>(phn, pw1 + wF, b1 + i * kFF,
                                            nullptr, nullptr, pff, kFF, kD, 2);
        float* cdst = (i == kL - 1) ? out : ph;
        mma_gemm<<<gProj, 256, kSmemBytes>>>(pff, pw2 + wF, b2 + i * kD,
                                             ph, cdst, nullptr, kD, kFF, 1);
    }
}

// round 15
// speedup vs baseline: 1.0986x; 1.0986x over previous
#include <cuda_runtime.h>
#include <cuda_fp16.h>
#include <math.h>
#include <stdint.h>

// ---------------------------------------------------------------------------
// Bert_Traj_Model: B=32, S=512, D=768, H=12, dh=64, FF=3072, L=12, fp32 I/O.
// Round 15: revert the .ca experiment (regression) -> all cp.async .cg, exact
// round-13 compute path. New: embed fused into the first LayerNorm (removes a
// 100MB g_tmp round-trip + one launch), bit-identical math.
// ---------------------------------------------------------------------------

namespace {
constexpr int kB  = 32;
constexpr int kS  = 512;
constexpr int kD  = 768;
constexpr int kH  = 12;
constexpr int kFF = 3072;
constexpr int kL  = 12;
constexpr int kM  = kB * kS;               // 16384 rows
constexpr int kQKV = 3 * kD;               // 2304
constexpr int kStageBytes = 16384;         // A 8K, B 8K
constexpr int kNS = 6;
constexpr int kSmemBytes = kNS * kStageBytes;       // 96KB
constexpr int kAttnSmem = 16384 + 2 * 16384 + 512;  // 49664
}

// ----------------------------- scratch (no allocs allowed) ------------------
__device__ float g_h  [(size_t)kM * kD];
__device__ float g_pe [kS * kD];
__device__ float g_bqkv[kL * kQKV];
__device__ __half g_hn [(size_t)kM * kD];
__device__ __half g_qkv[(size_t)kM * kQKV];
__device__ __half g_o  [(size_t)kM * kD];
__device__ __half g_ff [(size_t)kM * kFF];
// pre-tiled fp16 weights: blocks of 128(n) x 32(k), row-major in block
__device__ __half g_wqkv[(size_t)kL * kD * kQKV];
__device__ __half g_wo  [(size_t)kL * kD * kD];
__device__ __half g_w1  [(size_t)kL * kD * kFF];
__device__ __half g_w2  [(size_t)kL * kFF * kD];

// ----------------------------- PTX helpers ---------------------------------
__device__ __forceinline__ uint32_t smem_u32(const void* p) {
    uint32_t a;
    asm("{ .reg .u64 t; cvta.to.shared.u64 t, %1; cvt.u32.u64 %0, t; }" : "=r"(a) : "l"(p));
    return a;
}
#define CP16(dst, src) asm volatile("cp.async.cg.shared.global [%0], [%1], 16;" :: "r"(dst), "l"(src))
#define CP_COMMIT()    asm volatile("cp.async.commit_group;" ::: "memory")
#define CP_WAIT(n)     asm volatile("cp.async.wait_group %0;" :: "n"(n) : "memory")

#define LDSM4(r0, r1, r2, r3, a)                                                \
    asm volatile("ldmatrix.sync.aligned.m8n8.x4.shared.b16 {%0,%1,%2,%3}, [%4];" \
                 : "=r"(r0), "=r"(r1), "=r"(r2), "=r"(r3) : "r"(a))
#define LDSM4T(r0, r1, r2, r3, a)                                               \
    asm volatile("ldmatrix.sync.aligned.m8n8.x4.trans.shared.b16 {%0,%1,%2,%3}, [%4];" \
                 : "=r"(r0), "=r"(r1), "=r"(r2), "=r"(r3) : "r"(a))
#define MMA_F16(d, a, b)                                                        \
    asm volatile("mma.sync.aligned.m16n8k16.row.col.f32.f16.f16.f32 "           \
                 "{%0,%1,%2,%3}, {%4,%5,%6,%7}, {%8,%9}, {%0,%1,%2,%3};"        \
                 : "+f"((d)[0]), "+f"((d)[1]), "+f"((d)[2]), "+f"((d)[3])       \
                 : "r"((a)[0]), "r"((a)[1]), "r"((a)[2]), "r"((a)[3]),          \
                   "r"((b)[0]), "r"((b)[1]))

__device__ __forceinline__ uint32_t pack2h(float a, float b) {
    __half2 t = __halves2half2(__float2half_rn(a), __float2half_rn(b));
    return *(uint32_t*)&t;
}
__device__ __forceinline__ uint32_t soff(int row, int ch) {   // 64B rows
    return (uint32_t)(row * 64 + ((ch ^ ((row >> 1) & 3)) << 4));
}
__device__ __forceinline__ uint32_t swz(int row, int ch) {    // 128B rows
    return (uint32_t)(row * 128 + ((ch ^ (row & 7)) << 4));
}

// ---------------------------------------------------------------------------
// Weight prep (tile-mapped, division-free, coalesced).
// ---------------------------------------------------------------------------
__global__ void __launch_bounds__(256)
prep_w_tile(const float* __restrict__ W, __half* __restrict__ dst,
            int K, int Nsrc, int Ntot, int ntoff, float scale) {
    const int kc = blockIdx.x, nt = blockIdx.y, l = blockIdx.z;
    const int lane = threadIdx.x & 31, w = threadIdx.x >> 5;
    const int nl8 = lane >> 2, kkg = lane & 3;
    const int kcnt = K >> 5;
    const float* src = W + (size_t)l * K * Nsrc + (size_t)(kc * 32) * Nsrc + nt * 128;
    __half* dtile = dst + (size_t)l * K * Ntot
                  + ((size_t)((ntoff + nt) * kcnt + kc)) * 4096;
    #pragma unroll
    for (int task = 0; task < 2; task++) {
        const int nlb = (w + task * 8) * 8;        // 0,8,...,120
        const float* s0 = src + nlb + nl8;
        uint4 o;
        __half* oh = (__half*)&o;
        #pragma unroll
        for (int j = 0; j < 8; j++)
            oh[j] = __float2half_rn(s0[(size_t)(kkg * 8 + j) * Nsrc] * scale);
        *(uint4*)(dtile + (nlb + nl8) * 32 + kkg * 8) = o;
    }
}

__global__ void bias_qkv_kernel(const float* __restrict__ bq, const float* __restrict__ bk,
                                const float* __restrict__ bv, float* __restrict__ dst) {
    int idx = blockIdx.x * blockDim.x + threadIdx.x;
    if (idx >= kL * kQKV) return;
    int l = idx / kQKV, j = idx - l * kQKV;
    float v;
    if (j < kD)            v = 0.125f * bq[l * kD + j];
    else if (j < 2 * kD)   v = bk[l * kD + j - kD];
    else                   v = bv[l * kD + j - 2 * kD];
    dst[idx] = v;
}

// ---------------------------------------------------------------------------
// mma_gemm: C[M,N] = epi(A @ W + bias). A single fp16, W fp16 tiles (all .cg).
// modes: 1=+Res fp32 out, 2=relu fp16 out, 3=fp16 out.
// 128x128 CTA tile, 8 warps of 32x64, 6-stage cp.async, 1 barrier / 2 chunks.
// ---------------------------------------------------------------------------
__global__ void __launch_bounds__(256, 2)
mma_gemm(const __half* __restrict__ Ah, const __half* __restrict__ Bw,
         const float* __restrict__ bias, const float* __restrict__ Res,
         float* __restrict__ C, __half* __restrict__ Ch,
         int N, int K, int mode) {
    extern __shared__ char smem[];
    const uint32_t sb = smem_u32(smem);
    const int tid = threadIdx.x;
    const int lane = tid & 31, wid = tid >> 5;
    const int wm = (wid & 3) * 32, wn = (wid >> 2) * 64;
    const int m0 = blockIdx.y * 128, n0 = blockIdx.x * 128;
    const int iters = K >> 5;                       // even (>= 24)
    const size_t btile = (size_t)blockIdx.x * iters * 4096;

    float acc[2][8][4];
    #pragma unroll
    for (int a = 0; a < 2; a++)
        #pragma unroll
        for (int b = 0; b < 8; b++)
            #pragma unroll
            for (int c = 0; c < 4; c++) acc[a][b][c] = 0.0f;

    auto load_stage = [&](int c, int s) {
        const uint32_t st = sb + (uint32_t)s * kStageBytes;
        #pragma unroll
        for (int p = 0; p < 2; p++) {
            int idx = p * 256 + tid;
            int row = idx >> 2, ch = idx & 3;
            uint32_t so = soff(row, ch);
            const __half* gA = Ah + (size_t)(m0 + row) * K + c * 32 + ch * 8;
            size_t boff = btile + (size_t)c * 4096 + row * 32 + ch * 8;
            CP16(st + so, gA);
            CP16(st + 8192 + so, Bw + boff);
        }
        CP_COMMIT();
    };

    auto compute_stage = [&](int s) {
        const uint32_t base = sb + (uint32_t)s * kStageBytes;
        #pragma unroll
        for (int ks = 0; ks < 2; ks++) {
            const int kc = ks * 2;
            uint32_t ah[2][4], bh[8][2];
            #pragma unroll
            for (int mf = 0; mf < 2; mf++) {
                int row = wm + mf * 16 + (lane & 15);
                int ch = kc + (lane >> 4);
                LDSM4(ah[mf][0], ah[mf][1], ah[mf][2], ah[mf][3], base + soff(row, ch));
            }
            #pragma unroll
            for (int nb = 0; nb < 4; nb++) {
                int row = wn + nb * 16 + (lane & 7) + ((lane >> 4) << 3);
                int ch = kc + ((lane >> 3) & 1);
                LDSM4(bh[2 * nb][0], bh[2 * nb][1], bh[2 * nb + 1][0], bh[2 * nb + 1][1],
                      base + 8192 + soff(row, ch));
            }
            #pragma unroll
            for (int mf = 0; mf < 2; mf++)
                #pragma unroll
                for (int nf = 0; nf < 8; nf++)
                    MMA_F16(acc[mf][nf], ah[mf], bh[nf]);
        }
    };

    load_stage(0, 0);
    load_stage(1, 1);
    load_stage(2, 2);
    load_stage(3, 3);

    int s = 0;                                   // stage of chunk c
    for (int c = 0; c < iters; c += 2) {
        if (iters - c - 2 >= 2) CP_WAIT(2);
        else CP_WAIT(0);
        __syncthreads();
        if (c + 4 < iters) {
            int s4 = s + 4 >= 6 ? s - 2 : s + 4;
            int s5 = s4 + 1 >= 6 ? 0 : s4 + 1;
            load_stage(c + 4, s4);
            load_stage(c + 5, s5);
        }
        compute_stage(s);
        int s1 = s + 1 >= 6 ? 0 : s + 1;
        compute_stage(s1);
        s = s + 2 >= 6 ? s - 4 : s + 2;
    }

    #pragma unroll
    for (int mf = 0; mf < 2; mf++) {
        #pragma unroll
        for (int h = 0; h < 2; h++) {
            const int r = m0 + wm + mf * 16 + (lane >> 2) + h * 8;
            #pragma unroll
            for (int nf = 0; nf < 8; nf++) {
                const int cc = n0 + wn + nf * 8 + (lane & 3) * 2;
                float v0 = acc[mf][nf][h * 2 + 0] + bias[cc];
                float v1 = acc[mf][nf][h * 2 + 1] + bias[cc + 1];
                size_t base = (size_t)r * N + cc;
                if (mode == 3) {
                    *(uint32_t*)(Ch + base) = pack2h(v0, v1);
                } else if (mode == 2) {
                    v0 = fmaxf(v0, 0.0f);
                    v1 = fmaxf(v1, 0.0f);
                    *(uint32_t*)(Ch + base) = pack2h(v0, v1);
                } else {
                    float2 rr = *(const float2*)(Res + base);
                    float2 o;
                    o.x = v0 + rr.x;
                    o.y = v1 + rr.y;
                    *(float2*)(C + base) = o;
                }
            }
        }
    }
}

// ---------------------------------------------------------------------------
// attn_mma: flash attention, all-single-fp16 operands (fp32 accumulators).
// Causal tile-skip: kt < min(8, 2*qt+2).
// smem: Qh 16K | 2 stages x (Kh 8K|Vh 8K) | pad 512   (2 CTA/SM)
// ---------------------------------------------------------------------------
__global__ void __launch_bounds__(256, 2)
attn_mma(const __half* __restrict__ qh_g, const __half* __restrict__ kh_g,
         const __half* __restrict__ vh_g, int rstride,
         const int* __restrict__ xtok, const int* __restrict__ ltp,
         __half* __restrict__ oh_g) {
    extern __shared__ char smem[];
    const uint32_t sb = smem_u32(smem);
    const int tid = threadIdx.x, lane = tid & 31, w = tid >> 5;
    const int qt = blockIdx.x, hh = blockIdx.y, b = blockIdx.z;
    const int lt = ltp[0];
    const int nkt = (2 * qt + 2) < 8 ? (2 * qt + 2) : 8;   // live key tiles

    const uint32_t QH = sb;
    const uint32_t STG = sb + 16384;      // + s*16384: Kh 8K, Vh 8K
    char* padp = smem + 16384 + 2 * 16384;

    #pragma unroll
    for (int i = 0; i < 2; i++)
        padp[tid + i * 256] = (xtok[b * kS + tid + i * 256] > 0) ? 1 : 0;

    const size_t qgbase = ((size_t)(b * kS + qt * 128)) * rstride + hh * 64;
    #pragma unroll
    for (int i = 0; i < 4; i++) {
        int idx = i * 256 + tid;
        int row = idx >> 3, ch = idx & 7;
        CP16(QH + swz(row, ch), qh_g + qgbase + (size_t)row * rstride + ch * 8);
    }
    CP_COMMIT();

    auto load_kv = [&](int kt, int s) {
        const uint32_t st = STG + (uint32_t)s * 16384;
        const size_t gb = ((size_t)(b * kS + kt * 64)) * rstride + hh * 64;
        #pragma unroll
        for (int i = 0; i < 2; i++) {
            int idx = i * 256 + tid;
            int row = idx >> 3, ch = idx & 7;
            uint32_t so = swz(row, ch);
            size_t go = gb + (size_t)row * rstride + ch * 8;
            CP16(st + so,        kh_g + go);
            CP16(st + 8192 + so, vh_g + go);
        }
        CP_COMMIT();
    };

    load_kv(0, 0);
    load_kv(1, 1);

    uint32_t qfh[4][4];
    float oacc[8][4];
    #pragma unroll
    for (int i = 0; i < 8; i++)
        #pragma unroll
        for (int j = 0; j < 4; j++) oacc[i][j] = 0.0f;
    float m_[2] = {-INFINITY, -INFINITY}, l_[2] = {0.0f, 0.0f};

    const int rbase = qt * 128 + w * 16 + (lane >> 2);

    for (int kt = 0; kt < nkt; kt++) {
        if (kt < nkt - 1) { CP_WAIT(1); } else { CP_WAIT(0); }
        __syncthreads();

        if (kt == 0) {
            #pragma unroll
            for (int ks = 0; ks < 4; ks++) {
                int row = w * 16 + (lane & 15);
                int ch = ks * 2 + (lane >> 4);
                LDSM4(qfh[ks][0], qfh[ks][1], qfh[ks][2], qfh[ks][3], QH + swz(row, ch));
            }
        }

        const uint32_t st = STG + (uint32_t)(kt & 1) * 16384;
        const uint32_t KHs = st, VHs = st + 8192;

        float s4[8][4];
        #pragma unroll
        for (int i = 0; i < 8; i++)
            #pragma unroll
            for (int j = 0; j < 4; j++) s4[i][j] = 0.0f;

        #pragma unroll
        for (int ks = 0; ks < 4; ks++) {
            uint32_t bh[8][2];
            #pragma unroll
            for (int kg = 0; kg < 4; kg++) {
                int row = kg * 16 + (lane & 7) + ((lane >> 4) << 3);
                int ch = ks * 2 + ((lane >> 3) & 1);
                LDSM4(bh[2 * kg][0], bh[2 * kg][1], bh[2 * kg + 1][0], bh[2 * kg + 1][1],
                      KHs + swz(row, ch));
            }
            #pragma unroll
            for (int nf = 0; nf < 8; nf++)
                MMA_F16(s4[nf], qfh[ks], bh[nf]);
        }

        #pragma unroll
        for (int nf = 0; nf < 8; nf++) {
            int col = kt * 64 + nf * 8 + (lane & 3) * 2;
            bool p0 = padp[col] != 0;
            bool p1 = padp[col + 1] != 0;
            bool c0lt = col < lt, c1lt = (col + 1) < lt;
            s4[nf][0] = (p0 && (col <= rbase || c0lt))         ? s4[nf][0] : -1.0e9f;
            s4[nf][1] = (p1 && (col + 1 <= rbase || c1lt))     ? s4[nf][1] : -1.0e9f;
            s4[nf][2] = (p0 && (col <= rbase + 8 || c0lt))     ? s4[nf][2] : -1.0e9f;
            s4[nf][3] = (p1 && (col + 1 <= rbase + 8 || c1lt)) ? s4[nf][3] : -1.0e9f;
        }

        #pragma unroll
        for (int r = 0; r < 2; r++) {
            float tm = -INFINITY;
            #pragma unroll
            for (int nf = 0; nf < 8; nf++)
                tm = fmaxf(tm, fmaxf(s4[nf][2 * r], s4[nf][2 * r + 1]));
            tm = fmaxf(tm, __shfl_xor_sync(0xffffffffu, tm, 1));
            tm = fmaxf(tm, __shfl_xor_sync(0xffffffffu, tm, 2));
            float nm = fmaxf(m_[r], tm);
            float al = __expf(m_[r] - nm);
            m_[r] = nm;
            float ts = 0.0f;
            #pragma unroll
            for (int nf = 0; nf < 8; nf++) {
                float p0 = __expf(s4[nf][2 * r] - nm);
                float p1 = __expf(s4[nf][2 * r + 1] - nm);
                s4[nf][2 * r] = p0;
                s4[nf][2 * r + 1] = p1;
                ts += p0 + p1;
            }
            ts += __shfl_xor_sync(0xffffffffu, ts, 1);
            ts += __shfl_xor_sync(0xffffffffu, ts, 2);
            l_[r] = l_[r] * al + ts;
            #pragma unroll
            for (int nf = 0; nf < 8; nf++) {
                oacc[nf][2 * r] *= al;
                oacc[nf][2 * r + 1] *= al;
            }
        }

        // ---- O += P V (single fp16 products) ----
        #pragma unroll
        for (int kv = 0; kv < 4; kv++) {
            uint32_t pah[4];
            pah[0] = pack2h(s4[2 * kv][0], s4[2 * kv][1]);
            pah[1] = pack2h(s4[2 * kv][2], s4[2 * kv][3]);
            pah[2] = pack2h(s4[2 * kv + 1][0], s4[2 * kv + 1][1]);
            pah[3] = pack2h(s4[2 * kv + 1][2], s4[2 * kv + 1][3]);
            #pragma unroll
            for (int dg = 0; dg < 4; dg++) {
                int row = kv * 16 + (lane & 7) + ((lane >> 3) & 1) * 8;
                int ch = dg * 2 + (lane >> 4);
                uint32_t so = swz(row, ch);
                uint32_t vh0, vh1, vh2, vh3;
                LDSM4T(vh0, vh1, vh2, vh3, VHs + so);
                uint32_t bfh0[2] = {vh0, vh1}, bfh1[2] = {vh2, vh3};
                MMA_F16(oacc[dg * 2], pah, bfh0);
                MMA_F16(oacc[dg * 2 + 1], pah, bfh1);
            }
        }

        __syncthreads();
        if (kt + 2 < nkt) load_kv(kt + 2, kt & 1);
    }

    float inv0 = 1.0f / l_[0], inv1 = 1.0f / l_[1];
    const int row0 = qt * 128 + w * 16 + (lane >> 2);
    #pragma unroll
    for (int nf = 0; nf < 8; nf++) {
        int col = hh * 64 + nf * 8 + (lane & 3) * 2;
        size_t b0 = ((size_t)(b * kS + row0)) * kD + col;
        size_t b1 = ((size_t)(b * kS + row0 + 8)) * kD + col;
        *(uint32_t*)(oh_g + b0) = pack2h(oacc[nf][0] * inv0, oacc[nf][1] * inv0);
        *(uint32_t*)(oh_g + b1) = pack2h(oacc[nf][2] * inv1, oacc[nf][3] * inv1);
    }
}

// ---------------------------------------------------------------------------
// Positional encoding table (fp64, 393K elems).
// ---------------------------------------------------------------------------
__global__ void pe_kernel(float* __restrict__ pe) {
    int idx = blockIdx.x * blockDim.x + threadIdx.x;
    if (idx >= kS * kD) return;
    int s = idx / kD;
    int j = idx - s * kD;
    int i2 = j & ~1;
    double ang = (double)s * pow(10000.0, -(double)i2 / (double)kD);
    pe[idx] = (j & 1) ? (float)cos(ang) : (float)sin(ang);
}

// ----------------------------- LayerNorm ------------------------------------
__device__ __forceinline__ float block_reduce_sum(float v, float* sred) {
    #pragma unroll
    for (int o = 16; o > 0; o >>= 1) v += __shfl_xor_sync(0xffffffffu, v, o);
    int w = threadIdx.x >> 5;
    __syncthreads();
    if ((threadIdx.x & 31) == 0) sred[w] = v;
    __syncthreads();
    if (threadIdx.x == 0) {
        float t = sred[0];
        #pragma unroll
        for (int i = 1; i < 8; i++) t += sred[i];
        sred[0] = t;
    }
    __syncthreads();
    return sred[0];
}

// Fused embed + first LayerNorm: value = tok_emb[x] + time_emb[t] + pe, then LN.
// One block (256 threads) per row; identical add order to the reference.
__global__ void embed_ln_kernel(const int* __restrict__ x, const int* __restrict__ tim,
                                const float* __restrict__ tok_emb,
                                const float* __restrict__ time_emb,
                                const float* __restrict__ pe,
                                const float* __restrict__ g, const float* __restrict__ b,
                                float* __restrict__ out) {
    __shared__ float sred[8];
    int row = blockIdx.x, tid = threadIdx.x;
    int s = row & (kS - 1);
    const float* te = tok_emb + (size_t)x[row] * kD;
    const float* me = time_emb + (size_t)tim[row] * kD;
    const float* pp = pe + (size_t)s * kD;
    float v0 = te[tid]       + me[tid]       + pp[tid];
    float v1 = te[tid + 256] + me[tid + 256] + pp[tid + 256];
    float v2 = te[tid + 512] + me[tid + 512] + pp[tid + 512];
    float sum = block_reduce_sum(v0 + v1 + v2, sred);
    float mu = sum * (1.0f / 768.0f);
    float d0 = v0 - mu, d1 = v1 - mu, d2 = v2 - mu;
    float sq = block_reduce_sum(d0 * d0 + d1 * d1 + d2 * d2, sred);
    float inv = 1.0f / sqrtf(sq * (1.0f / 768.0f) + 1e-6f);
    float* op = out + (size_t)row * kD;
    op[tid]       = g[tid]       * d0 * inv + b[tid];
    op[tid + 256] = g[tid + 256] * d1 * inv + b[tid + 256];
    op[tid + 512] = g[tid + 512] * d2 * inv + b[tid + 512];
}

// Per-layer LN (fp16 out): warp-per-row, no block barriers, float4 I/O.
__global__ void __launch_bounds__(256, 8)
ln_h16_kernel(const float* __restrict__ in, __half* __restrict__ out,
              const float* __restrict__ g, const float* __restrict__ b) {
    const int row = blockIdx.x * 8 + (threadIdx.x >> 5);
    const int lane = threadIdx.x & 31;
    const float* ip = in + (size_t)row * kD + lane * 4;

    float4 v[6];
    float sum = 0.0f;
    #pragma unroll
    for (int i = 0; i < 6; i++) {
        v[i] = *(const float4*)(ip + i * 128);
        sum += (v[i].x + v[i].y) + (v[i].z + v[i].w);
    }
    #pragma unroll
    for (int o = 16; o > 0; o >>= 1) sum += __shfl_xor_sync(0xffffffffu, sum, o);
    const float mu = sum * (1.0f / 768.0f);

    float sq = 0.0f;
    #pragma unroll
    for (int i = 0; i < 6; i++) {
        v[i].x -= mu; v[i].y -= mu; v[i].z -= mu; v[i].w -= mu;
        sq += (v[i].x * v[i].x + v[i].y * v[i].y) + (v[i].z * v[i].z + v[i].w * v[i].w);
    }
    #pragma unroll
    for (int o = 16; o > 0; o >>= 1) sq += __shfl_xor_sync(0xffffffffu, sq, o);
    const float inv = rsqrtf(sq * (1.0f / 768.0f) + 1e-6f);

    __half* op = out + (size_t)row * kD + lane * 4;
    #pragma unroll
    for (int i = 0; i < 6; i++) {
        float4 gv = *(const float4*)(g + lane * 4 + i * 128);
        float4 bv = *(const float4*)(b + lane * 4 + i * 128);
        float r0 = gv.x * v[i].x * inv + bv.x;
        float r1 = gv.y * v[i].y * inv + bv.y;
        float r2 = gv.z * v[i].z * inv + bv.z;
        float r3 = gv.w * v[i].w * inv + bv.w;
        uint2 pk = {pack2h(r0, r1), pack2h(r2, r3)};
        *(uint2*)(op + i * 128) = pk;
    }
}

// ---------------------------------------------------------------------------
extern "C" void kernel_launch(void* const* d_in, const int* in_sizes, int n_in,
                              void* d_out, int out_size) {
    const int*   x        = (const int*)d_in[0];
    const int*   tim      = (const int*)d_in[1];
    const int*   len_traj = (const int*)d_in[2];
    const float* tok_emb  = (const float*)d_in[3];
    const float* time_emb = (const float*)d_in[4];
    const float* emb_g    = (const float*)d_in[5];
    const float* emb_b    = (const float*)d_in[6];
    const float* Wq = (const float*)d_in[7];
    const float* bq = (const float*)d_in[8];
    const float* Wk = (const float*)d_in[9];
    const float* bk = (const float*)d_in[10];
    const float* Wv = (const float*)d_in[11];
    const float* bv = (const float*)d_in[12];
    const float* Wo = (const float*)d_in[13];
    const float* bo = (const float*)d_in[14];
    const float* ln1_g = (const float*)d_in[15];
    const float* ln1_b = (const float*)d_in[16];
    const float* W1 = (const float*)d_in[17];
    const float* b1 = (const float*)d_in[18];
    const float* W2 = (const float*)d_in[19];
    const float* b2 = (const float*)d_in[20];
    const float* ln2_g = (const float*)d_in[21];
    const float* ln2_b = (const float*)d_in[22];
    float* out = (float*)d_out;

    float *ph, *ppe, *pbqkv;
    __half *phn, *pqkv, *po, *pff;
    __half *pwqkv, *pwo, *pw1, *pw2;
    cudaGetSymbolAddress((void**)&ph,    g_h);
    cudaGetSymbolAddress((void**)&ppe,   g_pe);
    cudaGetSymbolAddress((void**)&pbqkv, g_bqkv);
    cudaGetSymbolAddress((void**)&phn,   g_hn);
    cudaGetSymbolAddress((void**)&pqkv,  g_qkv);
    cudaGetSymbolAddress((void**)&po,    g_o);
    cudaGetSymbolAddress((void**)&pff,   g_ff);
    cudaGetSymbolAddress((void**)&pwqkv, g_wqkv);
    cudaGetSymbolAddress((void**)&pwo,   g_wo);
    cudaGetSymbolAddress((void**)&pw1,   g_w1);
    cudaGetSymbolAddress((void**)&pw2,   g_w2);

    cudaFuncSetAttribute(mma_gemm, cudaFuncAttributeMaxDynamicSharedMemorySize, kSmemBytes);
    cudaFuncSetAttribute(attn_mma, cudaFuncAttributeMaxDynamicSharedMemorySize, kAttnSmem);

    // weight prep: tile-mapped, division-free, coalesced
    prep_w_tile<<<dim3(24,  6, kL), 256>>>(Wq, pwqkv, kD,  kD,  kQKV, 0,  0.125f);
    prep_w_tile<<<dim3(24,  6, kL), 256>>>(Wk, pwqkv, kD,  kD,  kQKV, 6,  1.0f);
    prep_w_tile<<<dim3(24,  6, kL), 256>>>(Wv, pwqkv, kD,  kD,  kQKV, 12, 1.0f);
    prep_w_tile<<<dim3(24,  6, kL), 256>>>(Wo, pwo,   kD,  kD,  kD,   0,  1.0f);
    prep_w_tile<<<dim3(24, 24, kL), 256>>>(W1, pw1,   kD,  kFF, kFF,  0,  1.0f);
    prep_w_tile<<<dim3(96,  6, kL), 256>>>(W2, pw2,   kFF, kD,  kD,   0,  1.0f);
    bias_qkv_kernel<<<(kL * kQKV + 255) / 256, 256>>>(bq, bk, bv, pbqkv);

    pe_kernel<<<(kS * kD + 255) / 256, 256>>>(ppe);
    embed_ln_kernel<<<kM, 256>>>(x, tim, tok_emb, time_emb, ppe, emb_g, emb_b, ph);

    const dim3 gQKV(kQKV / 128, kM / 128);   // 18 x 128
    const dim3 gProj(kD / 128, kM / 128);    // 6 x 128
    const dim3 gFF1(kFF / 128, kM / 128);    // 24 x 128
    const dim3 gAttn(kS / 128, kH, kB);

    for (int i = 0; i < kL; i++) {
        const size_t wQ = (size_t)i * kD * kQKV;
        const size_t wD = (size_t)i * kD * kD;
        const size_t wF = (size_t)i * kD * kFF;
        ln_h16_kernel<<<kM / 8, 256>>>(ph, phn, ln1_g + i * kD, ln1_b + i * kD);
        mma_gemm<<<gQKV, 256, kSmemBytes>>>(phn, pwqkv + wQ, pbqkv + i * kQKV,
                                            nullptr, nullptr, pqkv, kQKV, kD, 3);
        attn_mma<<<gAttn, 256, kAttnSmem>>>(pqkv, pqkv + kD, pqkv + 2 * kD,
                                            kQKV, x, len_traj, po);
        mma_gemm<<<gProj, 256, kSmemBytes>>>(po, pwo + wD, bo + i * kD,
                                             ph, ph, nullptr, kD, kD, 1);
        ln_h16_kernel<<<kM / 8, 256>>>(ph, phn, ln2_g + i * kD, ln2_b + i * kD);
        mma_gemm<<<gFF1, 256, kSmemBytes>>>(phn, pw1 + wF, b1 + i * kFF,
                                            nullptr, nullptr, pff, kFF, kD, 2);
        float* cdst = (i == kL - 1) ? out : ph;
        mma_gemm<<<gProj, 256, kSmemBytes>>>(pff, pw2 + wF, b2 + i * kD,
                                             ph, cdst, nullptr, kD, kFF, 1);
    }
}

// round 16
// speedup vs baseline: 1.1739x; 1.0686x over previous
#include <cuda_runtime.h>
#include <cuda_fp16.h>
#include <math.h>
#include <stdint.h>

// ---------------------------------------------------------------------------
// Bert_Traj_Model: B=32, S=512, D=768, H=12, dh=64, FF=3072, L=12, fp32 I/O.
// Round 16: GEMM warp tile 64x64 (4 warps, 128 threads/CTA) to halve smem
// crossbar traffic per MMA (was the binding constraint: ~125 B/cyc demand vs
// 128 B/cyc limit with 32x64 warps). Pipeline/numerics identical to round 15.
// ---------------------------------------------------------------------------

namespace {
constexpr int kB  = 32;
constexpr int kS  = 512;
constexpr int kD  = 768;
constexpr int kH  = 12;
constexpr int kFF = 3072;
constexpr int kL  = 12;
constexpr int kM  = kB * kS;               // 16384 rows
constexpr int kQKV = 3 * kD;               // 2304
constexpr int kStageBytes = 16384;         // A 8K, B 8K
constexpr int kNS = 6;
constexpr int kSmemBytes = kNS * kStageBytes;       // 96KB
constexpr int kAttnSmem = 16384 + 2 * 16384 + 512;  // 49664
}

// ----------------------------- scratch (no allocs allowed) ------------------
__device__ float g_h  [(size_t)kM * kD];
__device__ float g_pe [kS * kD];
__device__ float g_bqkv[kL * kQKV];
__device__ __half g_hn [(size_t)kM * kD];
__device__ __half g_qkv[(size_t)kM * kQKV];
__device__ __half g_o  [(size_t)kM * kD];
__device__ __half g_ff [(size_t)kM * kFF];
// pre-tiled fp16 weights: blocks of 128(n) x 32(k), row-major in block
__device__ __half g_wqkv[(size_t)kL * kD * kQKV];
__device__ __half g_wo  [(size_t)kL * kD * kD];
__device__ __half g_w1  [(size_t)kL * kD * kFF];
__device__ __half g_w2  [(size_t)kL * kFF * kD];

// ----------------------------- PTX helpers ---------------------------------
__device__ __forceinline__ uint32_t smem_u32(const void* p) {
    uint32_t a;
    asm("{ .reg .u64 t; cvta.to.shared.u64 t, %1; cvt.u32.u64 %0, t; }" : "=r"(a) : "l"(p));
    return a;
}
#define CP16(dst, src) asm volatile("cp.async.cg.shared.global [%0], [%1], 16;" :: "r"(dst), "l"(src))
#define CP_COMMIT()    asm volatile("cp.async.commit_group;" ::: "memory")
#define CP_WAIT(n)     asm volatile("cp.async.wait_group %0;" :: "n"(n) : "memory")

#define LDSM4(r0, r1, r2, r3, a)                                                \
    asm volatile("ldmatrix.sync.aligned.m8n8.x4.shared.b16 {%0,%1,%2,%3}, [%4];" \
                 : "=r"(r0), "=r"(r1), "=r"(r2), "=r"(r3) : "r"(a))
#define LDSM4T(r0, r1, r2, r3, a)                                               \
    asm volatile("ldmatrix.sync.aligned.m8n8.x4.trans.shared.b16 {%0,%1,%2,%3}, [%4];" \
                 : "=r"(r0), "=r"(r1), "=r"(r2), "=r"(r3) : "r"(a))
#define MMA_F16(d, a, b)                                                        \
    asm volatile("mma.sync.aligned.m16n8k16.row.col.f32.f16.f16.f32 "           \
                 "{%0,%1,%2,%3}, {%4,%5,%6,%7}, {%8,%9}, {%0,%1,%2,%3};"        \
                 : "+f"((d)[0]), "+f"((d)[1]), "+f"((d)[2]), "+f"((d)[3])       \
                 : "r"((a)[0]), "r"((a)[1]), "r"((a)[2]), "r"((a)[3]),          \
                   "r"((b)[0]), "r"((b)[1]))

__device__ __forceinline__ uint32_t pack2h(float a, float b) {
    __half2 t = __halves2half2(__float2half_rn(a), __float2half_rn(b));
    return *(uint32_t*)&t;
}
__device__ __forceinline__ uint32_t soff(int row, int ch) {   // 64B rows
    return (uint32_t)(row * 64 + ((ch ^ ((row >> 1) & 3)) << 4));
}
__device__ __forceinline__ uint32_t swz(int row, int ch) {    // 128B rows
    return (uint32_t)(row * 128 + ((ch ^ (row & 7)) << 4));
}

// ---------------------------------------------------------------------------
// Weight prep (tile-mapped, division-free, coalesced).
// ---------------------------------------------------------------------------
__global__ void __launch_bounds__(256)
prep_w_tile(const float* __restrict__ W, __half* __restrict__ dst,
            int K, int Nsrc, int Ntot, int ntoff, float scale) {
    const int kc = blockIdx.x, nt = blockIdx.y, l = blockIdx.z;
    const int lane = threadIdx.x & 31, w = threadIdx.x >> 5;
    const int nl8 = lane >> 2, kkg = lane & 3;
    const int kcnt = K >> 5;
    const float* src = W + (size_t)l * K * Nsrc + (size_t)(kc * 32) * Nsrc + nt * 128;
    __half* dtile = dst + (size_t)l * K * Ntot
                  + ((size_t)((ntoff + nt) * kcnt + kc)) * 4096;
    #pragma unroll
    for (int task = 0; task < 2; task++) {
        const int nlb = (w + task * 8) * 8;        // 0,8,...,120
        const float* s0 = src + nlb + nl8;
        uint4 o;
        __half* oh = (__half*)&o;
        #pragma unroll
        for (int j = 0; j < 8; j++)
            oh[j] = __float2half_rn(s0[(size_t)(kkg * 8 + j) * Nsrc] * scale);
        *(uint4*)(dtile + (nlb + nl8) * 32 + kkg * 8) = o;
    }
}

__global__ void bias_qkv_kernel(const float* __restrict__ bq, const float* __restrict__ bk,
                                const float* __restrict__ bv, float* __restrict__ dst) {
    int idx = blockIdx.x * blockDim.x + threadIdx.x;
    if (idx >= kL * kQKV) return;
    int l = idx / kQKV, j = idx - l * kQKV;
    float v;
    if (j < kD)            v = 0.125f * bq[l * kD + j];
    else if (j < 2 * kD)   v = bk[l * kD + j - kD];
    else                   v = bv[l * kD + j - 2 * kD];
    dst[idx] = v;
}

// ---------------------------------------------------------------------------
// mma_gemm: C[M,N] = epi(A @ W + bias). A single fp16, W fp16 tiles (.cg).
// modes: 1=+Res fp32 out, 2=relu fp16 out, 3=fp16 out.
// 128x128 CTA tile, 4 warps of 64x64, 6-stage cp.async, 1 barrier / 2 chunks,
// 2 CTA/SM. Same per-element accumulation order as round 15 (bit-identical).
// ---------------------------------------------------------------------------
__global__ void __launch_bounds__(128, 2)
mma_gemm(const __half* __restrict__ Ah, const __half* __restrict__ Bw,
         const float* __restrict__ bias, const float* __restrict__ Res,
         float* __restrict__ C, __half* __restrict__ Ch,
         int N, int K, int mode) {
    extern __shared__ char smem[];
    const uint32_t sb = smem_u32(smem);
    const int tid = threadIdx.x;
    const int lane = tid & 31, wid = tid >> 5;     // 4 warps
    const int wm = (wid & 1) * 64, wn = (wid >> 1) * 64;
    const int m0 = blockIdx.y * 128, n0 = blockIdx.x * 128;
    const int iters = K >> 5;                       // even (>= 24)
    const size_t btile = (size_t)blockIdx.x * iters * 4096;

    float acc[4][8][4];
    #pragma unroll
    for (int a = 0; a < 4; a++)
        #pragma unroll
        for (int b = 0; b < 8; b++)
            #pragma unroll
            for (int c = 0; c < 4; c++) acc[a][b][c] = 0.0f;

    auto load_stage = [&](int c, int s) {
        const uint32_t st = sb + (uint32_t)s * kStageBytes;
        #pragma unroll
        for (int p = 0; p < 4; p++) {
            int idx = p * 128 + tid;                // 0..511
            int row = idx >> 2, ch = idx & 3;
            uint32_t so = soff(row, ch);
            const __half* gA = Ah + (size_t)(m0 + row) * K + c * 32 + ch * 8;
            size_t boff = btile + (size_t)c * 4096 + row * 32 + ch * 8;
            CP16(st + so, gA);
            CP16(st + 8192 + so, Bw + boff);
        }
        CP_COMMIT();
    };

    auto compute_stage = [&](int s) {
        const uint32_t base = sb + (uint32_t)s * kStageBytes;
        #pragma unroll
        for (int ks = 0; ks < 2; ks++) {
            const int kc = ks * 2;
            uint32_t ah[4][4], bh[8][2];
            #pragma unroll
            for (int mf = 0; mf < 4; mf++) {
                int row = wm + mf * 16 + (lane & 15);
                int ch = kc + (lane >> 4);
                LDSM4(ah[mf][0], ah[mf][1], ah[mf][2], ah[mf][3], base + soff(row, ch));
            }
            #pragma unroll
            for (int nb = 0; nb < 4; nb++) {
                int row = wn + nb * 16 + (lane & 7) + ((lane >> 4) << 3);
                int ch = kc + ((lane >> 3) & 1);
                LDSM4(bh[2 * nb][0], bh[2 * nb][1], bh[2 * nb + 1][0], bh[2 * nb + 1][1],
                      base + 8192 + soff(row, ch));
            }
            #pragma unroll
            for (int mf = 0; mf < 4; mf++)
                #pragma unroll
                for (int nf = 0; nf < 8; nf++)
                    MMA_F16(acc[mf][nf], ah[mf], bh[nf]);
        }
    };

    load_stage(0, 0);
    load_stage(1, 1);
    load_stage(2, 2);
    load_stage(3, 3);

    int s = 0;                                   // stage of chunk c
    for (int c = 0; c < iters; c += 2) {
        if (iters - c - 2 >= 2) CP_WAIT(2);
        else CP_WAIT(0);
        __syncthreads();
        if (c + 4 < iters) {
            int s4 = s + 4 >= 6 ? s - 2 : s + 4;
            int s5 = s4 + 1 >= 6 ? 0 : s4 + 1;
            load_stage(c + 4, s4);
            load_stage(c + 5, s5);
        }
        compute_stage(s);
        int s1 = s + 1 >= 6 ? 0 : s + 1;
        compute_stage(s1);
        s = s + 2 >= 6 ? s - 4 : s + 2;
    }

    #pragma unroll
    for (int mf = 0; mf < 4; mf++) {
        #pragma unroll
        for (int h = 0; h < 2; h++) {
            const int r = m0 + wm + mf * 16 + (lane >> 2) + h * 8;
            #pragma unroll
            for (int nf = 0; nf < 8; nf++) {
                const int cc = n0 + wn + nf * 8 + (lane & 3) * 2;
                float v0 = acc[mf][nf][h * 2 + 0] + bias[cc];
                float v1 = acc[mf][nf][h * 2 + 1] + bias[cc + 1];
                size_t base = (size_t)r * N + cc;
                if (mode == 3) {
                    *(uint32_t*)(Ch + base) = pack2h(v0, v1);
                } else if (mode == 2) {
                    v0 = fmaxf(v0, 0.0f);
                    v1 = fmaxf(v1, 0.0f);
                    *(uint32_t*)(Ch + base) = pack2h(v0, v1);
                } else {
                    float2 rr = *(const float2*)(Res + base);
                    float2 o;
                    o.x = v0 + rr.x;
                    o.y = v1 + rr.y;
                    *(float2*)(C + base) = o;
                }
            }
        }
    }
}

// ---------------------------------------------------------------------------
// attn_mma: flash attention, all-single-fp16 operands (fp32 accumulators).
// Causal tile-skip: kt < min(8, 2*qt+2).
// smem: Qh 16K | 2 stages x (Kh 8K|Vh 8K) | pad 512   (2 CTA/SM)
// ---------------------------------------------------------------------------
__global__ void __launch_bounds__(256, 2)
attn_mma(const __half* __restrict__ qh_g, const __half* __restrict__ kh_g,
         const __half* __restrict__ vh_g, int rstride,
         const int* __restrict__ xtok, const int* __restrict__ ltp,
         __half* __restrict__ oh_g) {
    extern __shared__ char smem[];
    const uint32_t sb = smem_u32(smem);
    const int tid = threadIdx.x, lane = tid & 31, w = tid >> 5;
    const int qt = blockIdx.x, hh = blockIdx.y, b = blockIdx.z;
    const int lt = ltp[0];
    const int nkt = (2 * qt + 2) < 8 ? (2 * qt + 2) : 8;   // live key tiles

    const uint32_t QH = sb;
    const uint32_t STG = sb + 16384;      // + s*16384: Kh 8K, Vh 8K
    char* padp = smem + 16384 + 2 * 16384;

    #pragma unroll
    for (int i = 0; i < 2; i++)
        padp[tid + i * 256] = (xtok[b * kS + tid + i * 256] > 0) ? 1 : 0;

    const size_t qgbase = ((size_t)(b * kS + qt * 128)) * rstride + hh * 64;
    #pragma unroll
    for (int i = 0; i < 4; i++) {
        int idx = i * 256 + tid;
        int row = idx >> 3, ch = idx & 7;
        CP16(QH + swz(row, ch), qh_g + qgbase + (size_t)row * rstride + ch * 8);
    }
    CP_COMMIT();

    auto load_kv = [&](int kt, int s) {
        const uint32_t st = STG + (uint32_t)s * 16384;
        const size_t gb = ((size_t)(b * kS + kt * 64)) * rstride + hh * 64;
        #pragma unroll
        for (int i = 0; i < 2; i++) {
            int idx = i * 256 + tid;
            int row = idx >> 3, ch = idx & 7;
            uint32_t so = swz(row, ch);
            size_t go = gb + (size_t)row * rstride + ch * 8;
            CP16(st + so,        kh_g + go);
            CP16(st + 8192 + so, vh_g + go);
        }
        CP_COMMIT();
    };

    load_kv(0, 0);
    load_kv(1, 1);

    uint32_t qfh[4][4];
    float oacc[8][4];
    #pragma unroll
    for (int i = 0; i < 8; i++)
        #pragma unroll
        for (int j = 0; j < 4; j++) oacc[i][j] = 0.0f;
    float m_[2] = {-INFINITY, -INFINITY}, l_[2] = {0.0f, 0.0f};

    const int rbase = qt * 128 + w * 16 + (lane >> 2);

    for (int kt = 0; kt < nkt; kt++) {
        if (kt < nkt - 1) { CP_WAIT(1); } else { CP_WAIT(0); }
        __syncthreads();

        if (kt == 0) {
            #pragma unroll
            for (int ks = 0; ks < 4; ks++) {
                int row = w * 16 + (lane & 15);
                int ch = ks * 2 + (lane >> 4);
                LDSM4(qfh[ks][0], qfh[ks][1], qfh[ks][2], qfh[ks][3], QH + swz(row, ch));
            }
        }

        const uint32_t st = STG + (uint32_t)(kt & 1) * 16384;
        const uint32_t KHs = st, VHs = st + 8192;

        float s4[8][4];
        #pragma unroll
        for (int i = 0; i < 8; i++)
            #pragma unroll
            for (int j = 0; j < 4; j++) s4[i][j] = 0.0f;

        #pragma unroll
        for (int ks = 0; ks < 4; ks++) {
            uint32_t bh[8][2];
            #pragma unroll
            for (int kg = 0; kg < 4; kg++) {
                int row = kg * 16 + (lane & 7) + ((lane >> 4) << 3);
                int ch = ks * 2 + ((lane >> 3) & 1);
                LDSM4(bh[2 * kg][0], bh[2 * kg][1], bh[2 * kg + 1][0], bh[2 * kg + 1][1],
                      KHs + swz(row, ch));
            }
            #pragma unroll
            for (int nf = 0; nf < 8; nf++)
                MMA_F16(s4[nf], qfh[ks], bh[nf]);
        }

        #pragma unroll
        for (int nf = 0; nf < 8; nf++) {
            int col = kt * 64 + nf * 8 + (lane & 3) * 2;
            bool p0 = padp[col] != 0;
            bool p1 = padp[col + 1] != 0;
            bool c0lt = col < lt, c1lt = (col + 1) < lt;
            s4[nf][0] = (p0 && (col <= rbase || c0lt))         ? s4[nf][0] : -1.0e9f;
            s4[nf][1] = (p1 && (col + 1 <= rbase || c1lt))     ? s4[nf][1] : -1.0e9f;
            s4[nf][2] = (p0 && (col <= rbase + 8 || c0lt))     ? s4[nf][2] : -1.0e9f;
            s4[nf][3] = (p1 && (col + 1 <= rbase + 8 || c1lt)) ? s4[nf][3] : -1.0e9f;
        }

        #pragma unroll
        for (int r = 0; r < 2; r++) {
            float tm = -INFINITY;
            #pragma unroll
            for (int nf = 0; nf < 8; nf++)
                tm = fmaxf(tm, fmaxf(s4[nf][2 * r], s4[nf][2 * r + 1]));
            tm = fmaxf(tm, __shfl_xor_sync(0xffffffffu, tm, 1));
            tm = fmaxf(tm, __shfl_xor_sync(0xffffffffu, tm, 2));
            float nm = fmaxf(m_[r], tm);
            float al = __expf(m_[r] - nm);
            m_[r] = nm;
            float ts = 0.0f;
            #pragma unroll
            for (int nf = 0; nf < 8; nf++) {
                float p0 = __expf(s4[nf][2 * r] - nm);
                float p1 = __expf(s4[nf][2 * r + 1] - nm);
                s4[nf][2 * r] = p0;
                s4[nf][2 * r + 1] = p1;
                ts += p0 + p1;
            }
            ts += __shfl_xor_sync(0xffffffffu, ts, 1);
            ts += __shfl_xor_sync(0xffffffffu, ts, 2);
            l_[r] = l_[r] * al + ts;
            #pragma unroll
            for (int nf = 0; nf < 8; nf++) {
                oacc[nf][2 * r] *= al;
                oacc[nf][2 * r + 1] *= al;
            }
        }

        // ---- O += P V (single fp16 products) ----
        #pragma unroll
        for (int kv = 0; kv < 4; kv++) {
            uint32_t pah[4];
            pah[0] = pack2h(s4[2 * kv][0], s4[2 * kv][1]);
            pah[1] = pack2h(s4[2 * kv][2], s4[2 * kv][3]);
            pah[2] = pack2h(s4[2 * kv + 1][0], s4[2 * kv + 1][1]);
            pah[3] = pack2h(s4[2 * kv + 1][2], s4[2 * kv + 1][3]);
            #pragma unroll
            for (int dg = 0; dg < 4; dg++) {
                int row = kv * 16 + (lane & 7) + ((lane >> 3) & 1) * 8;
                int ch = dg * 2 + (lane >> 4);
                uint32_t so = swz(row, ch);
                uint32_t vh0, vh1, vh2, vh3;
                LDSM4T(vh0, vh1, vh2, vh3, VHs + so);
                uint32_t bfh0[2] = {vh0, vh1}, bfh1[2] = {vh2, vh3};
                MMA_F16(oacc[dg * 2], pah, bfh0);
                MMA_F16(oacc[dg * 2 + 1], pah, bfh1);
            }
        }

        __syncthreads();
        if (kt + 2 < nkt) load_kv(kt + 2, kt & 1);
    }

    float inv0 = 1.0f / l_[0], inv1 = 1.0f / l_[1];
    const int row0 = qt * 128 + w * 16 + (lane >> 2);
    #pragma unroll
    for (int nf = 0; nf < 8; nf++) {
        int col = hh * 64 + nf * 8 + (lane & 3) * 2;
        size_t b0 = ((size_t)(b * kS + row0)) * kD + col;
        size_t b1 = ((size_t)(b * kS + row0 + 8)) * kD + col;
        *(uint32_t*)(oh_g + b0) = pack2h(oacc[nf][0] * inv0, oacc[nf][1] * inv0);
        *(uint32_t*)(oh_g + b1) = pack2h(oacc[nf][2] * inv1, oacc[nf][3] * inv1);
    }
}

// ---------------------------------------------------------------------------
// Positional encoding table (fp64, 393K elems).
// ---------------------------------------------------------------------------
__global__ void pe_kernel(float* __restrict__ pe) {
    int idx = blockIdx.x * blockDim.x + threadIdx.x;
    if (idx >= kS * kD) return;
    int s = idx / kD;
    int j = idx - s * kD;
    int i2 = j & ~1;
    double ang = (double)s * pow(10000.0, -(double)i2 / (double)kD);
    pe[idx] = (j & 1) ? (float)cos(ang) : (float)sin(ang);
}

// ----------------------------- LayerNorm ------------------------------------
__device__ __forceinline__ float block_reduce_sum(float v, float* sred) {
    #pragma unroll
    for (int o = 16; o > 0; o >>= 1) v += __shfl_xor_sync(0xffffffffu, v, o);
    int w = threadIdx.x >> 5;
    __syncthreads();
    if ((threadIdx.x & 31) == 0) sred[w] = v;
    __syncthreads();
    if (threadIdx.x == 0) {
        float t = sred[0];
        #pragma unroll
        for (int i = 1; i < 8; i++) t += sred[i];
        sred[0] = t;
    }
    __syncthreads();
    return sred[0];
}

// Fused embed + first LayerNorm (bit-identical add order).
__global__ void embed_ln_kernel(const int* __restrict__ x, const int* __restrict__ tim,
                                const float* __restrict__ tok_emb,
                                const float* __restrict__ time_emb,
                                const float* __restrict__ pe,
                                const float* __restrict__ g, const float* __restrict__ b,
                                float* __restrict__ out) {
    __shared__ float sred[8];
    int row = blockIdx.x, tid = threadIdx.x;
    int s = row & (kS - 1);
    const float* te = tok_emb + (size_t)x[row] * kD;
    const float* me = time_emb + (size_t)tim[row] * kD;
    const float* pp = pe + (size_t)s * kD;
    float v0 = te[tid]       + me[tid]       + pp[tid];
    float v1 = te[tid + 256] + me[tid + 256] + pp[tid + 256];
    float v2 = te[tid + 512] + me[tid + 512] + pp[tid + 512];
    float sum = block_reduce_sum(v0 + v1 + v2, sred);
    float mu = sum * (1.0f / 768.0f);
    float d0 = v0 - mu, d1 = v1 - mu, d2 = v2 - mu;
    float sq = block_reduce_sum(d0 * d0 + d1 * d1 + d2 * d2, sred);
    float inv = 1.0f / sqrtf(sq * (1.0f / 768.0f) + 1e-6f);
    float* op = out + (size_t)row * kD;
    op[tid]       = g[tid]       * d0 * inv + b[tid];
    op[tid + 256] = g[tid + 256] * d1 * inv + b[tid + 256];
    op[tid + 512] = g[tid + 512] * d2 * inv + b[tid + 512];
}

// Per-layer LN (fp16 out): warp-per-row, no block barriers, float4 I/O.
__global__ void __launch_bounds__(256, 8)
ln_h16_kernel(const float* __restrict__ in, __half* __restrict__ out,
              const float* __restrict__ g, const float* __restrict__ b) {
    const int row = blockIdx.x * 8 + (threadIdx.x >> 5);
    const int lane = threadIdx.x & 31;
    const float* ip = in + (size_t)row * kD + lane * 4;

    float4 v[6];
    float sum = 0.0f;
    #pragma unroll
    for (int i = 0; i < 6; i++) {
        v[i] = *(const float4*)(ip + i * 128);
        sum += (v[i].x + v[i].y) + (v[i].z + v[i].w);
    }
    #pragma unroll
    for (int o = 16; o > 0; o >>= 1) sum += __shfl_xor_sync(0xffffffffu, sum, o);
    const float mu = sum * (1.0f / 768.0f);

    float sq = 0.0f;
    #pragma unroll
    for (int i = 0; i < 6; i++) {
        v[i].x -= mu; v[i].y -= mu; v[i].z -= mu; v[i].w -= mu;
        sq += (v[i].x * v[i].x + v[i].y * v[i].y) + (v[i].z * v[i].z + v[i].w * v[i].w);
    }
    #pragma unroll
    for (int o = 16; o > 0; o >>= 1) sq += __shfl_xor_sync(0xffffffffu, sq, o);
    const float inv = rsqrtf(sq * (1.0f / 768.0f) + 1e-6f);

    __half* op = out + (size_t)row * kD + lane * 4;
    #pragma unroll
    for (int i = 0; i < 6; i++) {
        float4 gv = *(const float4*)(g + lane * 4 + i * 128);
        float4 bv = *(const float4*)(b + lane * 4 + i * 128);
        float r0 = gv.x * v[i].x * inv + bv.x;
        float r1 = gv.y * v[i].y * inv + bv.y;
        float r2 = gv.z * v[i].z * inv + bv.z;
        float r3 = gv.w * v[i].w * inv + bv.w;
        uint2 pk = {pack2h(r0, r1), pack2h(r2, r3)};
        *(uint2*)(op + i * 128) = pk;
    }
}

// ---------------------------------------------------------------------------
extern "C" void kernel_launch(void* const* d_in, const int* in_sizes, int n_in,
                              void* d_out, int out_size) {
    const int*   x        = (const int*)d_in[0];
    const int*   tim      = (const int*)d_in[1];
    const int*   len_traj = (const int*)d_in[2];
    const float* tok_emb  = (const float*)d_in[3];
    const float* time_emb = (const float*)d_in[4];
    const float* emb_g    = (const float*)d_in[5];
    const float* emb_b    = (const float*)d_in[6];
    const float* Wq = (const float*)d_in[7];
    const float* bq = (const float*)d_in[8];
    const float* Wk = (const float*)d_in[9];
    const float* bk = (const float*)d_in[10];
    const float* Wv = (const float*)d_in[11];
    const float* bv = (const float*)d_in[12];
    const float* Wo = (const float*)d_in[13];
    const float* bo = (const float*)d_in[14];
    const float* ln1_g = (const float*)d_in[15];
    const float* ln1_b = (const float*)d_in[16];
    const float* W1 = (const float*)d_in[17];
    const float* b1 = (const float*)d_in[18];
    const float* W2 = (const float*)d_in[19];
    const float* b2 = (const float*)d_in[20];
    const float* ln2_g = (const float*)d_in[21];
    const float* ln2_b = (const float*)d_in[22];
    float* out = (float*)d_out;

    float *ph, *ppe, *pbqkv;
    __half *phn, *pqkv, *po, *pff;
    __half *pwqkv, *pwo, *pw1, *pw2;
    cudaGetSymbolAddress((void**)&ph,    g_h);
    cudaGetSymbolAddress((void**)&ppe,   g_pe);
    cudaGetSymbolAddress((void**)&pbqkv, g_bqkv);
    cudaGetSymbolAddress((void**)&phn,   g_hn);
    cudaGetSymbolAddress((void**)&pqkv,  g_qkv);
    cudaGetSymbolAddress((void**)&po,    g_o);
    cudaGetSymbolAddress((void**)&pff,   g_ff);
    cudaGetSymbolAddress((void**)&pwqkv, g_wqkv);
    cudaGetSymbolAddress((void**)&pwo,   g_wo);
    cudaGetSymbolAddress((void**)&pw1,   g_w1);
    cudaGetSymbolAddress((void**)&pw2,   g_w2);

    cudaFuncSetAttribute(mma_gemm, cudaFuncAttributeMaxDynamicSharedMemorySize, kSmemBytes);
    cudaFuncSetAttribute(attn_mma, cudaFuncAttributeMaxDynamicSharedMemorySize, kAttnSmem);

    // weight prep: tile-mapped, division-free, coalesced
    prep_w_tile<<<dim3(24,  6, kL), 256>>>(Wq, pwqkv, kD,  kD,  kQKV, 0,  0.125f);
    prep_w_tile<<<dim3(24,  6, kL), 256>>>(Wk, pwqkv, kD,  kD,  kQKV, 6,  1.0f);
    prep_w_tile<<<dim3(24,  6, kL), 256>>>(Wv, pwqkv, kD,  kD,  kQKV, 12, 1.0f);
    prep_w_tile<<<dim3(24,  6, kL), 256>>>(Wo, pwo,   kD,  kD,  kD,   0,  1.0f);
    prep_w_tile<<<dim3(24, 24, kL), 256>>>(W1, pw1,   kD,  kFF, kFF,  0,  1.0f);
    prep_w_tile<<<dim3(96,  6, kL), 256>>>(W2, pw2,   kFF, kD,  kD,   0,  1.0f);
    bias_qkv_kernel<<<(kL * kQKV + 255) / 256, 256>>>(bq, bk, bv, pbqkv);

    pe_kernel<<<(kS * kD + 255) / 256, 256>>>(ppe);
    embed_ln_kernel<<<kM, 256>>>(x, tim, tok_emb, time_emb, ppe, emb_g, emb_b, ph);

    const dim3 gQKV(kQKV / 128, kM / 128);   // 18 x 128
    const dim3 gProj(kD / 128, kM / 128);    // 6 x 128
    const dim3 gFF1(kFF / 128, kM / 128);    // 24 x 128
    const dim3 gAttn(kS / 128, kH, kB);

    for (int i = 0; i < kL; i++) {
        const size_t wQ = (size_t)i * kD * kQKV;
        const size_t wD = (size_t)i * kD * kD;
        const size_t wF = (size_t)i * kD * kFF;
        ln_h16_kernel<<<kM / 8, 256>>>(ph, phn, ln1_g + i * kD, ln1_b + i * kD);
        mma_gemm<<<gQKV, 128, kSmemBytes>>>(phn, pwqkv + wQ, pbqkv + i * kQKV,
                                            nullptr, nullptr, pqkv, kQKV, kD, 3);
        attn_mma<<<gAttn, 256, kAttnSmem>>>(pqkv, pqkv + kD, pqkv + 2 * kD,
                                            kQKV, x, len_traj, po);
        mma_gemm<<<gProj, 128, kSmemBytes>>>(po, pwo + wD, bo + i * kD,
                                             ph, ph, nullptr, kD, kD, 1);
        ln_h16_kernel<<<kM / 8, 256>>>(ph, phn, ln2_g + i * kD, ln2_b + i * kD);
        mma_gemm<<<gFF1, 128, kSmemBytes>>>(phn, pw1 + wF, b1 + i * kFF,
                                            nullptr, nullptr, pff, kFF, kD, 2);
        float* cdst = (i == kL - 1) ? out : ph;
        mma_gemm<<<gProj, 128, kSmemBytes>>>(pff, pw2 + wF, b2 + i * kD,
                                             ph, cdst, nullptr, kD, kFF, 1);
    }
}